// round 15
// baseline (speedup 1.0000x reference)
#include <cuda_runtime.h>
#include <cuda_fp16.h>
#include <cstdint>
#include <math.h>

#define SEQ   1024
#define DIM   1024
#define NHEAD 16
#define HDIM  64
#define BATCH 4
#define NTOK  (BATCH*SEQ)
#define NBH   (BATCH*NHEAD)

// ---------------- scratch (allocation-free rule) ----------------
__device__ __half g_xh[NTOK*DIM];
__device__ __half g_wh[4*DIM*DIM];
__device__ __half g_qh[NBH*SEQ*HDIM];
__device__ __half g_kh[NBH*SEQ*HDIM];
__device__ __half g_vh[NBH*SEQ*HDIM];
__device__ __half g_wah[NTOK*DIM];

// ---------------- PTX helpers ----------------
__device__ __forceinline__ uint32_t smem_u32(const void* p) {
    uint32_t a;
    asm("{ .reg .u64 t; cvta.to.shared.u64 t, %1; cvt.u32.u64 %0, t; }" : "=r"(a) : "l"(p));
    return a;
}
#define CPA16(d, s)  asm volatile("cp.async.cg.shared.global [%0], [%1], 16;" :: "r"(d), "l"(s) : "memory")
#define CPA_COMMIT() asm volatile("cp.async.commit_group;" ::: "memory")
#define CPA_WAIT(n)  asm volatile("cp.async.wait_group %0;" :: "n"(n) : "memory")

#define LDSM_X4(r, addr) \
    asm volatile("ldmatrix.sync.aligned.m8n8.x4.shared.b16 {%0,%1,%2,%3}, [%4];" \
        : "=r"((r)[0]), "=r"((r)[1]), "=r"((r)[2]), "=r"((r)[3]) : "r"(addr))
#define LDSM_X4T(r, addr) \
    asm volatile("ldmatrix.sync.aligned.m8n8.x4.trans.shared.b16 {%0,%1,%2,%3}, [%4];" \
        : "=r"((r)[0]), "=r"((r)[1]), "=r"((r)[2]), "=r"((r)[3]) : "r"(addr))

#define MMA16816(d, a, b0, b1) \
    asm volatile("mma.sync.aligned.m16n8k16.row.col.f32.f16.f16.f32 " \
        "{%0,%1,%2,%3}, {%4,%5,%6,%7}, {%8,%9}, {%0,%1,%2,%3};" \
        : "+f"((d)[0]), "+f"((d)[1]), "+f"((d)[2]), "+f"((d)[3]) \
        : "r"((a)[0]), "r"((a)[1]), "r"((a)[2]), "r"((a)[3]), "r"(b0), "r"(b1))

__device__ __forceinline__ uint32_t sw128(uint32_t boff) {
    return boff ^ ((boff >> 3) & 0x70);
}
__device__ __forceinline__ void pack_h2(float a, float b, uint32_t& h) {
    __half2 H; H.x = __float2half_rn(a); H.y = __float2half_rn(b);
    h = *(uint32_t*)&H;
}

struct GParams {
    const __half* Bh[3];
    const float*  bias[3];
    __half*       Ch[3];
    float*        Cf;
};

// ---------------------------------------------------------------------------
// mma.sync fp16 GEMM with REGISTER DOUBLE-BUFFERED fragments:
// LDSM for ks+1 issued before MMAs of ks -> LDSM latency hidden.
// C[128 x 64] per CTA, 256 thr = 8 warps (4m x 2n), warp tile 32x32.
// 2-stage cp.async pipeline, 2 CTAs/SM (16 warps/SM).
// EPI 0: fp32 out (ldc);  EPI 1: fp16 scatter [B,H,S,Hd]
// ---------------------------------------------------------------------------
template<int EPI>
__global__ void __launch_bounds__(256, 2)
tc_gemm(const __half* __restrict__ Ah, GParams gpar, int K, int lda, int ldb, int ldc)
{
    extern __shared__ char dsm[];
    constexpr int ABYTES = 128 * 128;        // 16 KB
    constexpr int BBYTES = 64 * 128;         // 8 KB
    constexpr int STG    = ABYTES + BBYTES;  // 24 KB

    const int tid    = threadIdx.x;
    const int lane   = tid & 31;
    const int wid    = tid >> 5;
    const int warp_m = wid & 3;
    const int warp_n = wid >> 2;
    const int row0   = blockIdx.y * 128;
    const int col0   = blockIdx.x * 64;
    const int z      = blockIdx.z;

    const __half* __restrict__ Bh  = gpar.Bh[z];
    const float* __restrict__ bias = gpar.bias[z];

    const uint32_t dyn0 = smem_u32(dsm);
    const uint32_t dyn  = (dyn0 + 1023) & ~1023u;

    const int nch = K / 64;

    auto load_chunk = [&](int c) {
        const uint32_t s = dyn + (c & 1) * STG;
        const int koff = c * 64;
        #pragma unroll
        for (int i = 0; i < 4; i++) {
            int lin = tid + i * 256;
            int r = lin >> 3, sg = lin & 7;
            uint32_t sw = sw128((uint32_t)(r * 128 + sg * 16));
            CPA16(s + sw, (const void*)(Ah + (long long)(row0 + r) * lda + koff + sg * 8));
        }
        #pragma unroll
        for (int i = 0; i < 2; i++) {
            int lin = tid + i * 256;
            int r = lin >> 3, sg = lin & 7;
            uint32_t sw = sw128((uint32_t)(r * 128 + sg * 16));
            CPA16(s + ABYTES + sw, (const void*)(Bh + (long long)(col0 + r) * ldb + koff + sg * 8));
        }
        CPA_COMMIT();
    };

    // per-lane fragment address precompute
    const int a_r0 = warp_m * 32 + (lane & 15);
    const int a_hi = (lane >> 4) * 16;
    const int b_q  = lane >> 3, b_rr = lane & 7;
    const int b_n0 = warp_n * 32 + ((b_q >> 1) << 3) + b_rr;
    const int b_k8 = (b_q & 1) * 8;

    float acc[2][4][4];
    #pragma unroll
    for (int i = 0; i < 2; i++)
        #pragma unroll
        for (int j = 0; j < 4; j++)
            #pragma unroll
            for (int q = 0; q < 4; q++) acc[i][j][q] = 0.f;

    uint32_t aF[2][2][4], bF[2][2][4];

    load_chunk(0);

    for (int c = 0; c < nch; c++) {
        if (c + 1 < nch) { load_chunk(c + 1); CPA_WAIT(1); }
        else             { CPA_WAIT(0); }
        __syncthreads();

        const uint32_t ah_ = dyn + (c & 1) * STG;
        const uint32_t bh_ = ah_ + ABYTES;

        // prologue: fragments for ks = 0
        {
            #pragma unroll
            for (int im = 0; im < 2; im++) {
                uint32_t bo = (uint32_t)((a_r0 + im * 16) * 128 + a_hi);
                LDSM_X4(aF[0][im], ah_ + sw128(bo));
            }
            #pragma unroll
            for (int jn = 0; jn < 2; jn++) {
                uint32_t bo = (uint32_t)((b_n0 + jn * 16) * 128 + b_k8 * 2);
                LDSM_X4(bF[0][jn], bh_ + sw128(bo));
            }
        }

        #pragma unroll
        for (int ks = 0; ks < 4; ks++) {
            const int cur = ks & 1;
            if (ks < 3) {
                const int nxt = cur ^ 1;
                const int kk = (ks + 1) * 16;
                #pragma unroll
                for (int im = 0; im < 2; im++) {
                    uint32_t bo = (uint32_t)((a_r0 + im * 16) * 128 + kk * 2 + a_hi);
                    LDSM_X4(aF[nxt][im], ah_ + sw128(bo));
                }
                #pragma unroll
                for (int jn = 0; jn < 2; jn++) {
                    uint32_t bo = (uint32_t)((b_n0 + jn * 16) * 128 + (kk + b_k8) * 2);
                    LDSM_X4(bF[nxt][jn], bh_ + sw128(bo));
                }
            }
            #pragma unroll
            for (int im = 0; im < 2; im++) {
                MMA16816(acc[im][0], aF[cur][im], bF[cur][0][0], bF[cur][0][1]);
                MMA16816(acc[im][1], aF[cur][im], bF[cur][0][2], bF[cur][0][3]);
                MMA16816(acc[im][2], aF[cur][im], bF[cur][1][0], bF[cur][1][1]);
                MMA16816(acc[im][3], aF[cur][im], bF[cur][1][2], bF[cur][1][3]);
            }
        }
        __syncthreads();
    }

    const int g = lane >> 2, t = lane & 3;
    #pragma unroll
    for (int im = 0; im < 2; im++) {
        #pragma unroll
        for (int in = 0; in < 4; in++) {
            const float* ac = acc[im][in];
            const int n0 = col0 + warp_n * 32 + in * 8 + t * 2;
            #pragma unroll
            for (int half_ = 0; half_ < 2; half_++) {
                const int m = row0 + warp_m * 32 + im * 16 + g + half_ * 8;
                float v0 = ac[half_ * 2]     + bias[n0];
                float v1 = ac[half_ * 2 + 1] + bias[n0 + 1];
                if (EPI == 0) {
                    *(float2*)(gpar.Cf + (long long)m * ldc + n0) = make_float2(v0, v1);
                } else {
                    int b = m >> 10, s = m & 1023, h = n0 >> 6, d = n0 & 63;
                    long long off = ((((long long)(b * NHEAD + h) << 10) + s) * HDIM) + d;
                    __half2 H; H.x = __float2half_rn(v0); H.y = __float2half_rn(v1);
                    *(__half2*)(gpar.Ch[z] + off) = H;
                }
            }
        }
    }
}

// ---------------------------------------------------------------------------
// Fused flash attention (R10 config — best measured; fp32 S accumulation).
// ---------------------------------------------------------------------------
__global__ void __launch_bounds__(256, 2)
flash_attn(const __half* __restrict__ qh, const __half* __restrict__ kh,
           const __half* __restrict__ vh, __half* __restrict__ wah)
{
    extern __shared__ char dsm[];
    const int tid  = threadIdx.x;
    const int lane = tid & 31;
    const int wid  = tid >> 5;
    const int z    = blockIdx.x;
    const int qrow0 = blockIdx.y * 128;

    const uint32_t dyn0 = smem_u32(dsm);
    const uint32_t dyn  = (dyn0 + 1023) & ~1023u;
    const uint32_t sQh = dyn;
    const uint32_t kvb = dyn + 16384;

    const long long zoff = (long long)z * SEQ * HDIM;
    const __half* Qh = qh + zoff;
    const __half* Kh = kh + zoff;
    const __half* Vh = vh + zoff;

    #pragma unroll
    for (int i = 0; i < 4; i++) {
        int lin = tid + i * 256;
        int r = lin >> 3, sg = lin & 7;
        uint32_t sw = sw128((uint32_t)(r * 128 + sg * 16));
        CPA16(sQh + sw, (const void*)(Qh + (long long)(qrow0 + r) * HDIM + sg * 8));
    }
    CPA_COMMIT();

    auto load_kv = [&](int c) {
        uint32_t b = kvb + (c & 1) * 16384;
        int kv0 = c * 64;
        #pragma unroll
        for (int i = 0; i < 2; i++) {
            int lin = tid + i * 256;
            int r = lin >> 3, sg = lin & 7;
            uint32_t sw = sw128((uint32_t)(r * 128 + sg * 16));
            long long go = (long long)(kv0 + r) * HDIM + sg * 8;
            CPA16(b +        sw, (const void*)(Kh + go));
            CPA16(b + 8192 + sw, (const void*)(Vh + go));
        }
        CPA_COMMIT();
    };
    load_kv(0);

    const int g = lane >> 2, t = lane & 3;
    float O[8][4];
    #pragma unroll
    for (int j = 0; j < 8; j++)
        #pragma unroll
        for (int q = 0; q < 4; q++) O[j][q] = 0.f;
    float m0 = -1e30f, m1 = -1e30f, l0 = 0.f, l1 = 0.f;

    const int NKV = SEQ / 64;
    for (int c = 0; c < NKV; c++) {
        if (c + 1 < NKV) { load_kv(c + 1); CPA_WAIT(1); }
        else             { CPA_WAIT(0); }
        __syncthreads();

        const uint32_t base = kvb + (c & 1) * 16384;
        const uint32_t bKh = base, bVh = base + 8192;

        float S[8][4];
        #pragma unroll
        for (int j = 0; j < 8; j++)
            #pragma unroll
            for (int q = 0; q < 4; q++) S[j][q] = 0.f;

        #pragma unroll
        for (int ks = 0; ks < 4; ks++) {
            uint32_t aH[4];
            {
                int r = wid * 16 + (lane & 15);
                uint32_t boff = (uint32_t)(r * 128 + ks * 32 + (lane >> 4) * 16);
                LDSM_X4(aH, sQh + sw128(boff));
            }
            #pragma unroll
            for (int gp = 0; gp < 2; gp++) {
                uint32_t bH0[4], bH1[4];
                const int q = lane >> 3, rr = lane & 7;
                int nr0 = (2 * gp)     * 16 + ((q >> 1) << 3) + rr;
                int nr1 = (2 * gp + 1) * 16 + ((q >> 1) << 3) + rr;
                uint32_t bo0 = (uint32_t)(nr0 * 128 + (ks * 16 + (q & 1) * 8) * 2);
                uint32_t bo1 = (uint32_t)(nr1 * 128 + (ks * 16 + (q & 1) * 8) * 2);
                LDSM_X4(bH0, bKh + sw128(bo0));
                LDSM_X4(bH1, bKh + sw128(bo1));
                MMA16816(S[4 * gp],     aH, bH0[0], bH0[1]);
                MMA16816(S[4 * gp + 1], aH, bH0[2], bH0[3]);
                MMA16816(S[4 * gp + 2], aH, bH1[0], bH1[1]);
                MMA16816(S[4 * gp + 3], aH, bH1[2], bH1[3]);
            }
        }

        float mx0 = -1e30f, mx1 = -1e30f;
        #pragma unroll
        for (int j = 0; j < 8; j++) {
            S[j][0] *= 0.125f; S[j][1] *= 0.125f; S[j][2] *= 0.125f; S[j][3] *= 0.125f;
            mx0 = fmaxf(mx0, fmaxf(S[j][0], S[j][1]));
            mx1 = fmaxf(mx1, fmaxf(S[j][2], S[j][3]));
        }
        mx0 = fmaxf(mx0, __shfl_xor_sync(0xffffffffu, mx0, 1));
        mx0 = fmaxf(mx0, __shfl_xor_sync(0xffffffffu, mx0, 2));
        mx1 = fmaxf(mx1, __shfl_xor_sync(0xffffffffu, mx1, 1));
        mx1 = fmaxf(mx1, __shfl_xor_sync(0xffffffffu, mx1, 2));
        float nm0 = fmaxf(m0, mx0), nm1 = fmaxf(m1, mx1);
        float c0 = __expf(m0 - nm0), c1 = __expf(m1 - nm1);
        m0 = nm0; m1 = nm1;

        uint32_t PH[4][4];
        float s0 = 0.f, s1 = 0.f;
        #pragma unroll
        for (int ck = 0; ck < 4; ck++) {
            float p00 = __expf(S[2 * ck][0] - nm0),   p01 = __expf(S[2 * ck][1] - nm0);
            float p02 = __expf(S[2 * ck][2] - nm1),   p03 = __expf(S[2 * ck][3] - nm1);
            float p10 = __expf(S[2 * ck + 1][0] - nm0), p11 = __expf(S[2 * ck + 1][1] - nm0);
            float p12 = __expf(S[2 * ck + 1][2] - nm1), p13 = __expf(S[2 * ck + 1][3] - nm1);
            s0 += p00 + p01 + p10 + p11;
            s1 += p02 + p03 + p12 + p13;
            pack_h2(p00, p01, PH[ck][0]);
            pack_h2(p02, p03, PH[ck][1]);
            pack_h2(p10, p11, PH[ck][2]);
            pack_h2(p12, p13, PH[ck][3]);
        }
        l0 = l0 * c0 + s0;
        l1 = l1 * c1 + s1;
        #pragma unroll
        for (int j = 0; j < 8; j++) {
            O[j][0] *= c0; O[j][1] *= c0; O[j][2] *= c1; O[j][3] *= c1;
        }

        #pragma unroll
        for (int ck = 0; ck < 4; ck++) {
            #pragma unroll
            for (int dp = 0; dp < 2; dp++) {
                uint32_t bH0[4], bH1[4];
                const int q = lane >> 3, rr = lane & 7;
                int kr = ck * 16 + (q & 1) * 8 + rr;
                int nc0 = (2 * dp)     * 16 + ((q >> 1) << 3);
                int nc1 = (2 * dp + 1) * 16 + ((q >> 1) << 3);
                uint32_t bo0 = (uint32_t)(kr * 128 + nc0 * 2);
                uint32_t bo1 = (uint32_t)(kr * 128 + nc1 * 2);
                LDSM_X4T(bH0, bVh + sw128(bo0));
                LDSM_X4T(bH1, bVh + sw128(bo1));
                MMA16816(O[4 * dp],     PH[ck], bH0[0], bH0[1]);
                MMA16816(O[4 * dp + 1], PH[ck], bH0[2], bH0[3]);
                MMA16816(O[4 * dp + 2], PH[ck], bH1[0], bH1[1]);
                MMA16816(O[4 * dp + 3], PH[ck], bH1[2], bH1[3]);
            }
        }
        __syncthreads();
    }

    l0 += __shfl_xor_sync(0xffffffffu, l0, 1);
    l0 += __shfl_xor_sync(0xffffffffu, l0, 2);
    l1 += __shfl_xor_sync(0xffffffffu, l1, 1);
    l1 += __shfl_xor_sync(0xffffffffu, l1, 2);
    float inv0 = 1.f / l0, inv1 = 1.f / l1;

    const int b = z >> 4, h = z & 15;
    const int r0 = qrow0 + wid * 16 + g;
    #pragma unroll
    for (int j = 0; j < 8; j++) {
        int d = j * 8 + t * 2;
        long long off0 = (((long long)(b << 10) + r0) << 10) + h * HDIM + d;
        long long off1 = (((long long)(b << 10) + r0 + 8) << 10) + h * HDIM + d;
        __half2 H0; H0.x = __float2half_rn(O[j][0] * inv0); H0.y = __float2half_rn(O[j][1] * inv0);
        __half2 H1; H1.x = __float2half_rn(O[j][2] * inv1); H1.y = __float2half_rn(O[j][3] * inv1);
        *(__half2*)(wah + off0) = H0;
        *(__half2*)(wah + off1) = H1;
    }
}

// ---------------------------------------------------------------------------
struct SplitP {
    const float* in[5];
    __half* hi[5];
};

__global__ void __launch_bounds__(256)
split_all(SplitP p)
{
    int idx = blockIdx.x * 256 + threadIdx.x;
    int r, local;
    if (idx < (1 << 20)) { r = 0; local = idx; }
    else {
        int t2 = idx - (1 << 20);
        r = 1 + (t2 >> 18);
        local = t2 & ((1 << 18) - 1);
    }
    float4 v = ((const float4*)p.in[r])[local];
    __half2 H0; H0.x = __float2half_rn(v.x); H0.y = __float2half_rn(v.y);
    __half2 H1; H1.x = __float2half_rn(v.z); H1.y = __float2half_rn(v.w);
    ((__half2*)p.hi[r])[2 * local]     = H0;
    ((__half2*)p.hi[r])[2 * local + 1] = H1;
}

// ---------------------------------------------------------------------------
extern "C" void kernel_launch(void* const* d_in, const int* in_sizes, int n_in,
                              void* d_out, int out_size)
{
    (void)in_sizes; (void)n_in; (void)out_size;
    const float* x  = (const float*)d_in[0];
    const float* Wq = (const float*)d_in[1];
    const float* bq = (const float*)d_in[2];
    const float* Wk = (const float*)d_in[3];
    const float* bk = (const float*)d_in[4];
    const float* Wv = (const float*)d_in[5];
    const float* bv = (const float*)d_in[6];
    const float* Wp = (const float*)d_in[7];
    const float* bp = (const float*)d_in[8];
    float* out = (float*)d_out;

    __half *xh, *wh, *qh, *kh, *vh, *wah;
    cudaGetSymbolAddress((void**)&xh,  g_xh);
    cudaGetSymbolAddress((void**)&wh,  g_wh);
    cudaGetSymbolAddress((void**)&qh,  g_qh);
    cudaGetSymbolAddress((void**)&kh,  g_kh);
    cudaGetSymbolAddress((void**)&vh,  g_vh);
    cudaGetSymbolAddress((void**)&wah, g_wah);

    const int SMGM = 2 * 24576 + 1024;             // 50176 (2 CTAs/SM)
    const int SMFA = 16384 + 2 * 16384 + 1024;     // 50176 (2 CTAs/SM)
    cudaFuncSetAttribute(tc_gemm<1>, cudaFuncAttributeMaxDynamicSharedMemorySize, SMGM);
    cudaFuncSetAttribute(tc_gemm<0>, cudaFuncAttributeMaxDynamicSharedMemorySize, SMGM);
    cudaFuncSetAttribute(flash_attn, cudaFuncAttributeMaxDynamicSharedMemorySize, SMFA);

    SplitP sp;
    sp.in[0] = x;  sp.hi[0] = xh;
    sp.in[1] = Wq; sp.hi[1] = wh + 0 * DIM * DIM;
    sp.in[2] = Wk; sp.hi[2] = wh + 1 * DIM * DIM;
    sp.in[3] = Wv; sp.hi[3] = wh + 2 * DIM * DIM;
    sp.in[4] = Wp; sp.hi[4] = wh + 3 * DIM * DIM;
    split_all<<<(1 << 20) / 256 + 4 * ((1 << 18) / 256), 256>>>(sp);

    // QKV projections (z selects weight set) -> fp16 [B,H,S,Hd]
    GParams gq = {};
    gq.Bh[0] = wh + 0 * DIM * DIM; gq.bias[0] = bq; gq.Ch[0] = qh;
    gq.Bh[1] = wh + 1 * DIM * DIM; gq.bias[1] = bk; gq.Ch[1] = kh;
    gq.Bh[2] = wh + 2 * DIM * DIM; gq.bias[2] = bv; gq.Ch[2] = vh;
    dim3 gp(DIM / 64, NTOK / 128, 3);
    tc_gemm<1><<<gp, 256, SMGM>>>(xh, gq, DIM, DIM, DIM, 0);

    dim3 gf(NBH, SEQ / 128);
    flash_attn<<<gf, 256, SMFA>>>(qh, kh, vh, wah);

    GParams go = {};
    go.Bh[0] = wh + 3 * DIM * DIM; go.bias[0] = bp; go.Cf = out;
    dim3 gop(DIM / 64, NTOK / 128, 1);
    tc_gemm<0><<<gop, 256, SMGM>>>(wah, go, DIM, DIM, DIM, DIM);
}

// round 16
// speedup vs baseline: 1.0862x; 1.0862x over previous
#include <cuda_runtime.h>
#include <cuda_fp16.h>
#include <cstdint>
#include <math.h>

#define SEQ   1024
#define DIM   1024
#define NHEAD 16
#define HDIM  64
#define BATCH 4
#define NTOK  (BATCH*SEQ)
#define NBH   (BATCH*NHEAD)

// ---------------- scratch (allocation-free rule) ----------------
__device__ __half g_xh[NTOK*DIM];                 // x fp16
__device__ __half g_wh[4*DIM*DIM];                // weights fp16
__device__ __half g_qh[NBH*SEQ*HDIM];             // Q [bh,s,d] (pre-scaled by 1/8)
__device__ __half g_kh[NBH*SEQ*HDIM];             // K
__device__ __half g_vh[NBH*SEQ*HDIM];             // V
__device__ __half g_wah[NTOK*DIM];                // wa [B,S,D]

// ---------------- PTX helpers ----------------
__device__ __forceinline__ uint32_t smem_u32(const void* p) {
    uint32_t a;
    asm("{ .reg .u64 t; cvta.to.shared.u64 t, %1; cvt.u32.u64 %0, t; }" : "=r"(a) : "l"(p));
    return a;
}
#define CPA16(d, s)  asm volatile("cp.async.cg.shared.global [%0], [%1], 16;" :: "r"(d), "l"(s) : "memory")
#define CPA_COMMIT() asm volatile("cp.async.commit_group;" ::: "memory")
#define CPA_WAIT(n)  asm volatile("cp.async.wait_group %0;" :: "n"(n) : "memory")

#define LDSM_X4(r, addr) \
    asm volatile("ldmatrix.sync.aligned.m8n8.x4.shared.b16 {%0,%1,%2,%3}, [%4];" \
        : "=r"((r)[0]), "=r"((r)[1]), "=r"((r)[2]), "=r"((r)[3]) : "r"(addr))
#define LDSM_X4T(r, addr) \
    asm volatile("ldmatrix.sync.aligned.m8n8.x4.trans.shared.b16 {%0,%1,%2,%3}, [%4];" \
        : "=r"((r)[0]), "=r"((r)[1]), "=r"((r)[2]), "=r"((r)[3]) : "r"(addr))

#define MMA16816(d, a, b0, b1) \
    asm volatile("mma.sync.aligned.m16n8k16.row.col.f32.f16.f16.f32 " \
        "{%0,%1,%2,%3}, {%4,%5,%6,%7}, {%8,%9}, {%0,%1,%2,%3};" \
        : "+f"((d)[0]), "+f"((d)[1]), "+f"((d)[2]), "+f"((d)[3]) \
        : "r"((a)[0]), "r"((a)[1]), "r"((a)[2]), "r"((a)[3]), "r"(b0), "r"(b1))

__device__ __forceinline__ uint32_t sw128(uint32_t boff) {
    return boff ^ ((boff >> 3) & 0x70);
}
__device__ __forceinline__ void pack_h2(float a, float b, uint32_t& h) {
    __half2 H; H.x = __float2half_rn(a); H.y = __float2half_rn(b);
    h = *(uint32_t*)&H;
}

struct GParams {
    const __half* Bh[3];
    const float*  bias[3];
    __half*       Ch[3];
    float         cscale[3];   // output scale per z (1/8 for Q, 1 otherwise)
    float*        Cf;
};

// ---------------------------------------------------------------------------
// mma.sync fp16 GEMM (exact R12 config — best measured).
// C[128 x 128] per CTA, 128 thr = 4 warps (2m x 2n), warp tile 64x64.
// 2-stage cp.async pipeline, 2 CTAs/SM.
// EPI 0: fp32 out (ldc);  EPI 1: fp16 scatter [B,H,S,Hd], scaled by cscale[z]
// ---------------------------------------------------------------------------
template<int EPI>
__global__ void __launch_bounds__(128, 2)
tc_gemm(const __half* __restrict__ Ah, GParams gpar, int K, int lda, int ldb, int ldc)
{
    extern __shared__ char dsm[];
    constexpr int ABYTES = 128 * 128;
    constexpr int BBYTES = 128 * 128;
    constexpr int STG    = ABYTES + BBYTES;  // 32 KB

    const int tid    = threadIdx.x;
    const int lane   = tid & 31;
    const int wid    = tid >> 5;
    const int warp_m = wid & 1;
    const int warp_n = wid >> 1;
    const int row0   = blockIdx.y * 128;
    const int col0   = blockIdx.x * 128;
    const int z      = blockIdx.z;

    const __half* __restrict__ Bh  = gpar.Bh[z];
    const float* __restrict__ bias = gpar.bias[z];
    const float cs = gpar.cscale[z];

    const uint32_t dyn0 = smem_u32(dsm);
    const uint32_t dyn  = (dyn0 + 1023) & ~1023u;

    const int nch = K / 64;

    auto load_chunk = [&](int c) {
        const uint32_t s = dyn + (c & 1) * STG;
        const int koff = c * 64;
        #pragma unroll
        for (int i = 0; i < 8; i++) {
            int lin = tid + i * 128;
            int r = lin >> 3, sg = lin & 7;
            uint32_t sw = sw128((uint32_t)(r * 128 + sg * 16));
            CPA16(s + sw, (const void*)(Ah + (long long)(row0 + r) * lda + koff + sg * 8));
        }
        #pragma unroll
        for (int i = 0; i < 8; i++) {
            int lin = tid + i * 128;
            int r = lin >> 3, sg = lin & 7;
            uint32_t sw = sw128((uint32_t)(r * 128 + sg * 16));
            CPA16(s + ABYTES + sw, (const void*)(Bh + (long long)(col0 + r) * ldb + koff + sg * 8));
        }
        CPA_COMMIT();
    };

    float acc[4][8][4];
    #pragma unroll
    for (int i = 0; i < 4; i++)
        #pragma unroll
        for (int j = 0; j < 8; j++)
            #pragma unroll
            for (int q = 0; q < 4; q++) acc[i][j][q] = 0.f;

    load_chunk(0);

    for (int c = 0; c < nch; c++) {
        if (c + 1 < nch) { load_chunk(c + 1); CPA_WAIT(1); }
        else             { CPA_WAIT(0); }
        __syncthreads();

        const uint32_t ah_ = dyn + (c & 1) * STG;
        const uint32_t bh_ = ah_ + ABYTES;

        #pragma unroll
        for (int ks = 0; ks < 4; ks++) {
            uint32_t bF[4][4];
            #pragma unroll
            for (int jn = 0; jn < 4; jn++) {
                const int q = lane >> 3, rr = lane & 7;
                int nr = warp_n * 64 + jn * 16 + ((q >> 1) << 3) + rr;
                uint32_t bo = (uint32_t)(nr * 128 + (ks * 16 + (q & 1) * 8) * 2);
                LDSM_X4(bF[jn], bh_ + sw128(bo));
            }
            uint32_t aF[4][4];
            #pragma unroll
            for (int im = 0; im < 4; im++) {
                int r = warp_m * 64 + im * 16 + (lane & 15);
                uint32_t bo = (uint32_t)(r * 128 + ks * 32 + (lane >> 4) * 16);
                LDSM_X4(aF[im], ah_ + sw128(bo));
            }
            #pragma unroll
            for (int im = 0; im < 4; im++) {
                #pragma unroll
                for (int jn = 0; jn < 4; jn++) {
                    MMA16816(acc[im][2 * jn],     aF[im], bF[jn][0], bF[jn][1]);
                    MMA16816(acc[im][2 * jn + 1], aF[im], bF[jn][2], bF[jn][3]);
                }
            }
        }
        __syncthreads();
    }

    const int g = lane >> 2, t = lane & 3;
    #pragma unroll
    for (int im = 0; im < 4; im++) {
        #pragma unroll
        for (int in = 0; in < 8; in++) {
            const float* ac = acc[im][in];
            const int n0 = col0 + warp_n * 64 + in * 8 + t * 2;
            #pragma unroll
            for (int half_ = 0; half_ < 2; half_++) {
                const int m = row0 + warp_m * 64 + im * 16 + g + half_ * 8;
                float v0 = ac[half_ * 2]     + bias[n0];
                float v1 = ac[half_ * 2 + 1] + bias[n0 + 1];
                if (EPI == 0) {
                    *(float2*)(gpar.Cf + (long long)m * ldc + n0) = make_float2(v0, v1);
                } else {
                    v0 *= cs; v1 *= cs;
                    int b = m >> 10, s = m & 1023, h = n0 >> 6, d = n0 & 63;
                    long long off = ((((long long)(b * NHEAD + h) << 10) + s) * HDIM) + d;
                    __half2 H; H.x = __float2half_rn(v0); H.y = __float2half_rn(v1);
                    *(__half2*)(gpar.Ch[z] + off) = H;
                }
            }
        }
    }
}

// ---------------------------------------------------------------------------
// Fused flash attention (R10/R12 config). Q is pre-scaled by 1/8 upstream,
// so S needs no scaling here.
// ---------------------------------------------------------------------------
__global__ void __launch_bounds__(256, 2)
flash_attn(const __half* __restrict__ qh, const __half* __restrict__ kh,
           const __half* __restrict__ vh, __half* __restrict__ wah)
{
    extern __shared__ char dsm[];
    const int tid  = threadIdx.x;
    const int lane = tid & 31;
    const int wid  = tid >> 5;
    const int z    = blockIdx.x;
    const int qrow0 = blockIdx.y * 128;

    const uint32_t dyn0 = smem_u32(dsm);
    const uint32_t dyn  = (dyn0 + 1023) & ~1023u;
    const uint32_t sQh = dyn;
    const uint32_t kvb = dyn + 16384;

    const long long zoff = (long long)z * SEQ * HDIM;
    const __half* Qh = qh + zoff;
    const __half* Kh = kh + zoff;
    const __half* Vh = vh + zoff;

    #pragma unroll
    for (int i = 0; i < 4; i++) {
        int lin = tid + i * 256;
        int r = lin >> 3, sg = lin & 7;
        uint32_t sw = sw128((uint32_t)(r * 128 + sg * 16));
        CPA16(sQh + sw, (const void*)(Qh + (long long)(qrow0 + r) * HDIM + sg * 8));
    }
    CPA_COMMIT();

    auto load_kv = [&](int c) {
        uint32_t b = kvb + (c & 1) * 16384;
        int kv0 = c * 64;
        #pragma unroll
        for (int i = 0; i < 2; i++) {
            int lin = tid + i * 256;
            int r = lin >> 3, sg = lin & 7;
            uint32_t sw = sw128((uint32_t)(r * 128 + sg * 16));
            long long go = (long long)(kv0 + r) * HDIM + sg * 8;
            CPA16(b +        sw, (const void*)(Kh + go));
            CPA16(b + 8192 + sw, (const void*)(Vh + go));
        }
        CPA_COMMIT();
    };
    load_kv(0);

    const int g = lane >> 2, t = lane & 3;
    float O[8][4];
    #pragma unroll
    for (int j = 0; j < 8; j++)
        #pragma unroll
        for (int q = 0; q < 4; q++) O[j][q] = 0.f;
    float m0 = -1e30f, m1 = -1e30f, l0 = 0.f, l1 = 0.f;

    const int NKV = SEQ / 64;
    for (int c = 0; c < NKV; c++) {
        if (c + 1 < NKV) { load_kv(c + 1); CPA_WAIT(1); }
        else             { CPA_WAIT(0); }
        __syncthreads();

        const uint32_t base = kvb + (c & 1) * 16384;
        const uint32_t bKh = base, bVh = base + 8192;

        float S[8][4];
        #pragma unroll
        for (int j = 0; j < 8; j++)
            #pragma unroll
            for (int q = 0; q < 4; q++) S[j][q] = 0.f;

        // ---- S = (Q/8) K^T ----
        #pragma unroll
        for (int ks = 0; ks < 4; ks++) {
            uint32_t aH[4];
            {
                int r = wid * 16 + (lane & 15);
                uint32_t boff = (uint32_t)(r * 128 + ks * 32 + (lane >> 4) * 16);
                LDSM_X4(aH, sQh + sw128(boff));
            }
            #pragma unroll
            for (int gp = 0; gp < 2; gp++) {
                uint32_t bH0[4], bH1[4];
                const int q = lane >> 3, rr = lane & 7;
                int nr0 = (2 * gp)     * 16 + ((q >> 1) << 3) + rr;
                int nr1 = (2 * gp + 1) * 16 + ((q >> 1) << 3) + rr;
                uint32_t bo0 = (uint32_t)(nr0 * 128 + (ks * 16 + (q & 1) * 8) * 2);
                uint32_t bo1 = (uint32_t)(nr1 * 128 + (ks * 16 + (q & 1) * 8) * 2);
                LDSM_X4(bH0, bKh + sw128(bo0));
                LDSM_X4(bH1, bKh + sw128(bo1));
                MMA16816(S[4 * gp],     aH, bH0[0], bH0[1]);
                MMA16816(S[4 * gp + 1], aH, bH0[2], bH0[3]);
                MMA16816(S[4 * gp + 2], aH, bH1[0], bH1[1]);
                MMA16816(S[4 * gp + 3], aH, bH1[2], bH1[3]);
            }
        }

        // ---- online softmax (no scale needed: Q pre-scaled) ----
        float mx0 = -1e30f, mx1 = -1e30f;
        #pragma unroll
        for (int j = 0; j < 8; j++) {
            mx0 = fmaxf(mx0, fmaxf(S[j][0], S[j][1]));
            mx1 = fmaxf(mx1, fmaxf(S[j][2], S[j][3]));
        }
        mx0 = fmaxf(mx0, __shfl_xor_sync(0xffffffffu, mx0, 1));
        mx0 = fmaxf(mx0, __shfl_xor_sync(0xffffffffu, mx0, 2));
        mx1 = fmaxf(mx1, __shfl_xor_sync(0xffffffffu, mx1, 1));
        mx1 = fmaxf(mx1, __shfl_xor_sync(0xffffffffu, mx1, 2));
        float nm0 = fmaxf(m0, mx0), nm1 = fmaxf(m1, mx1);
        float c0 = __expf(m0 - nm0), c1 = __expf(m1 - nm1);
        m0 = nm0; m1 = nm1;

        uint32_t PH[4][4];
        float s0 = 0.f, s1 = 0.f;
        #pragma unroll
        for (int ck = 0; ck < 4; ck++) {
            float p00 = __expf(S[2 * ck][0] - nm0),   p01 = __expf(S[2 * ck][1] - nm0);
            float p02 = __expf(S[2 * ck][2] - nm1),   p03 = __expf(S[2 * ck][3] - nm1);
            float p10 = __expf(S[2 * ck + 1][0] - nm0), p11 = __expf(S[2 * ck + 1][1] - nm0);
            float p12 = __expf(S[2 * ck + 1][2] - nm1), p13 = __expf(S[2 * ck + 1][3] - nm1);
            s0 += p00 + p01 + p10 + p11;
            s1 += p02 + p03 + p12 + p13;
            pack_h2(p00, p01, PH[ck][0]);
            pack_h2(p02, p03, PH[ck][1]);
            pack_h2(p10, p11, PH[ck][2]);
            pack_h2(p12, p13, PH[ck][3]);
        }
        l0 = l0 * c0 + s0;
        l1 = l1 * c1 + s1;
        #pragma unroll
        for (int j = 0; j < 8; j++) {
            O[j][0] *= c0; O[j][1] *= c0; O[j][2] *= c1; O[j][3] *= c1;
        }

        // ---- O += P V ----
        #pragma unroll
        for (int ck = 0; ck < 4; ck++) {
            #pragma unroll
            for (int dp = 0; dp < 2; dp++) {
                uint32_t bH0[4], bH1[4];
                const int q = lane >> 3, rr = lane & 7;
                int kr = ck * 16 + (q & 1) * 8 + rr;
                int nc0 = (2 * dp)     * 16 + ((q >> 1) << 3);
                int nc1 = (2 * dp + 1) * 16 + ((q >> 1) << 3);
                uint32_t bo0 = (uint32_t)(kr * 128 + nc0 * 2);
                uint32_t bo1 = (uint32_t)(kr * 128 + nc1 * 2);
                LDSM_X4T(bH0, bVh + sw128(bo0));
                LDSM_X4T(bH1, bVh + sw128(bo1));
                MMA16816(O[4 * dp],     PH[ck], bH0[0], bH0[1]);
                MMA16816(O[4 * dp + 1], PH[ck], bH0[2], bH0[3]);
                MMA16816(O[4 * dp + 2], PH[ck], bH1[0], bH1[1]);
                MMA16816(O[4 * dp + 3], PH[ck], bH1[2], bH1[3]);
            }
        }
        __syncthreads();
    }

    l0 += __shfl_xor_sync(0xffffffffu, l0, 1);
    l0 += __shfl_xor_sync(0xffffffffu, l0, 2);
    l1 += __shfl_xor_sync(0xffffffffu, l1, 1);
    l1 += __shfl_xor_sync(0xffffffffu, l1, 2);
    float inv0 = 1.f / l0, inv1 = 1.f / l1;

    const int b = z >> 4, h = z & 15;
    const int r0 = qrow0 + wid * 16 + g;
    #pragma unroll
    for (int j = 0; j < 8; j++) {
        int d = j * 8 + t * 2;
        long long off0 = (((long long)(b << 10) + r0) << 10) + h * HDIM + d;
        long long off1 = (((long long)(b << 10) + r0 + 8) << 10) + h * HDIM + d;
        __half2 H0; H0.x = __float2half_rn(O[j][0] * inv0); H0.y = __float2half_rn(O[j][1] * inv0);
        __half2 H1; H1.x = __float2half_rn(O[j][2] * inv1); H1.y = __float2half_rn(O[j][3] * inv1);
        *(__half2*)(wah + off0) = H0;
        *(__half2*)(wah + off1) = H1;
    }
}

// ---------------------------------------------------------------------------
// merged fp32 -> fp16 conversion for x + 4 weight matrices
// ---------------------------------------------------------------------------
struct SplitP {
    const float* in[5];
    __half* hi[5];
};

__global__ void __launch_bounds__(256)
split_all(SplitP p)
{
    int idx = blockIdx.x * 256 + threadIdx.x;
    int r, local;
    if (idx < (1 << 20)) { r = 0; local = idx; }
    else {
        int t2 = idx - (1 << 20);
        r = 1 + (t2 >> 18);
        local = t2 & ((1 << 18) - 1);
    }
    float4 v = ((const float4*)p.in[r])[local];
    __half2 H0; H0.x = __float2half_rn(v.x); H0.y = __float2half_rn(v.y);
    __half2 H1; H1.x = __float2half_rn(v.z); H1.y = __float2half_rn(v.w);
    ((__half2*)p.hi[r])[2 * local]     = H0;
    ((__half2*)p.hi[r])[2 * local + 1] = H1;
}

// ---------------------------------------------------------------------------
extern "C" void kernel_launch(void* const* d_in, const int* in_sizes, int n_in,
                              void* d_out, int out_size)
{
    (void)in_sizes; (void)n_in; (void)out_size;
    const float* x  = (const float*)d_in[0];
    const float* Wq = (const float*)d_in[1];
    const float* bq = (const float*)d_in[2];
    const float* Wk = (const float*)d_in[3];
    const float* bk = (const float*)d_in[4];
    const float* Wv = (const float*)d_in[5];
    const float* bv = (const float*)d_in[6];
    const float* Wp = (const float*)d_in[7];
    const float* bp = (const float*)d_in[8];
    float* out = (float*)d_out;

    __half *xh, *wh, *qh, *kh, *vh, *wah;
    cudaGetSymbolAddress((void**)&xh,  g_xh);
    cudaGetSymbolAddress((void**)&wh,  g_wh);
    cudaGetSymbolAddress((void**)&qh,  g_qh);
    cudaGetSymbolAddress((void**)&kh,  g_kh);
    cudaGetSymbolAddress((void**)&vh,  g_vh);
    cudaGetSymbolAddress((void**)&wah, g_wah);

    const int SMGM = 2 * 32768 + 1024;             // 66560 (2 CTAs/SM)
    const int SMFA = 16384 + 2 * 16384 + 1024;     // 50176 (2 CTAs/SM)
    cudaFuncSetAttribute(tc_gemm<1>, cudaFuncAttributeMaxDynamicSharedMemorySize, SMGM);
    cudaFuncSetAttribute(tc_gemm<0>, cudaFuncAttributeMaxDynamicSharedMemorySize, SMGM);
    cudaFuncSetAttribute(flash_attn, cudaFuncAttributeMaxDynamicSharedMemorySize, SMFA);

    SplitP sp;
    sp.in[0] = x;  sp.hi[0] = xh;
    sp.in[1] = Wq; sp.hi[1] = wh + 0 * DIM * DIM;
    sp.in[2] = Wk; sp.hi[2] = wh + 1 * DIM * DIM;
    sp.in[3] = Wv; sp.hi[3] = wh + 2 * DIM * DIM;
    sp.in[4] = Wp; sp.hi[4] = wh + 3 * DIM * DIM;
    split_all<<<(1 << 20) / 256 + 4 * ((1 << 18) / 256), 256>>>(sp);

    // QKV projections (z selects weight set) -> fp16 [B,H,S,Hd]
    // Q output pre-scaled by 1/8 (softmax scale folded upstream)
    GParams gq = {};
    gq.Bh[0] = wh + 0 * DIM * DIM; gq.bias[0] = bq; gq.Ch[0] = qh; gq.cscale[0] = 0.125f;
    gq.Bh[1] = wh + 1 * DIM * DIM; gq.bias[1] = bk; gq.Ch[1] = kh; gq.cscale[1] = 1.0f;
    gq.Bh[2] = wh + 2 * DIM * DIM; gq.bias[2] = bv; gq.Ch[2] = vh; gq.cscale[2] = 1.0f;
    dim3 gp(DIM / 128, NTOK / 128, 3);
    tc_gemm<1><<<gp, 128, SMGM>>>(xh, gq, DIM, DIM, DIM, 0);

    dim3 gf(NBH, SEQ / 128);
    flash_attn<<<gf, 256, SMFA>>>(qh, kh, vh, wah);

    GParams go = {};
    go.Bh[0] = wh + 3 * DIM * DIM; go.bias[0] = bp; go.Cf = out; go.cscale[0] = 1.0f;
    dim3 gop(DIM / 128, NTOK / 128, 1);
    tc_gemm<0><<<gop, 128, SMGM>>>(wah, go, DIM, DIM, DIM, DIM);
}

// round 17
// speedup vs baseline: 1.1219x; 1.0329x over previous
#include <cuda_runtime.h>
#include <cuda_fp16.h>
#include <cstdint>
#include <math.h>

#define SEQ   1024
#define DIM   1024
#define NHEAD 16
#define HDIM  64
#define BATCH 4
#define NTOK  (BATCH*SEQ)
#define NBH   (BATCH*NHEAD)

// ---------------- scratch (allocation-free rule) ----------------
__device__ __half g_xh[NTOK*DIM];                 // x fp16
__device__ __half g_wh[4*DIM*DIM];                // weights fp16
__device__ __half g_qh[NBH*SEQ*HDIM];             // Q [bh,s,d] (pre-scaled by 1/8)
__device__ __half g_kh[NBH*SEQ*HDIM];             // K
__device__ __half g_vh[NBH*SEQ*HDIM];             // V
__device__ __half g_wah[NTOK*DIM];                // wa [B,S,D]

// ---------------- PTX helpers ----------------
__device__ __forceinline__ uint32_t smem_u32(const void* p) {
    uint32_t a;
    asm("{ .reg .u64 t; cvta.to.shared.u64 t, %1; cvt.u32.u64 %0, t; }" : "=r"(a) : "l"(p));
    return a;
}
#define CPA16(d, s)  asm volatile("cp.async.cg.shared.global [%0], [%1], 16;" :: "r"(d), "l"(s) : "memory")
#define CPA_COMMIT() asm volatile("cp.async.commit_group;" ::: "memory")
#define CPA_WAIT(n)  asm volatile("cp.async.wait_group %0;" :: "n"(n) : "memory")

#define LDSM_X4(r, addr) \
    asm volatile("ldmatrix.sync.aligned.m8n8.x4.shared.b16 {%0,%1,%2,%3}, [%4];" \
        : "=r"((r)[0]), "=r"((r)[1]), "=r"((r)[2]), "=r"((r)[3]) : "r"(addr))
#define LDSM_X4T(r, addr) \
    asm volatile("ldmatrix.sync.aligned.m8n8.x4.trans.shared.b16 {%0,%1,%2,%3}, [%4];" \
        : "=r"((r)[0]), "=r"((r)[1]), "=r"((r)[2]), "=r"((r)[3]) : "r"(addr))

#define MMA16816(d, a, b0, b1) \
    asm volatile("mma.sync.aligned.m16n8k16.row.col.f32.f16.f16.f32 " \
        "{%0,%1,%2,%3}, {%4,%5,%6,%7}, {%8,%9}, {%0,%1,%2,%3};" \
        : "+f"((d)[0]), "+f"((d)[1]), "+f"((d)[2]), "+f"((d)[3]) \
        : "r"((a)[0]), "r"((a)[1]), "r"((a)[2]), "r"((a)[3]), "r"(b0), "r"(b1))

__device__ __forceinline__ uint32_t sw128(uint32_t boff) {
    return boff ^ ((boff >> 3) & 0x70);
}
__device__ __forceinline__ void pack_h2(float a, float b, uint32_t& h) {
    __half2 H; H.x = __float2half_rn(a); H.y = __float2half_rn(b);
    h = *(uint32_t*)&H;
}

struct GParams {
    const __half* Bh[3];
    const float*  bias[3];
    __half*       Ch[3];
    float         cscale[3];
    float*        Cf;
};

// ---------------------------------------------------------------------------
// mma.sync fp16 GEMM (R12 config — best measured).
// C[128 x 128] per CTA, 128 thr = 4 warps (2m x 2n), warp tile 64x64.
// 2-stage cp.async pipeline, 2 CTAs/SM.
// EPI 0: fp32 out (ldc);  EPI 1: fp16 scatter [B,H,S,Hd], scaled by cscale[z]
// ---------------------------------------------------------------------------
template<int EPI>
__global__ void __launch_bounds__(128, 2)
tc_gemm(const __half* __restrict__ Ah, GParams gpar, int K, int lda, int ldb, int ldc)
{
    extern __shared__ char dsm[];
    constexpr int ABYTES = 128 * 128;
    constexpr int BBYTES = 128 * 128;
    constexpr int STG    = ABYTES + BBYTES;  // 32 KB

    const int tid    = threadIdx.x;
    const int lane   = tid & 31;
    const int wid    = tid >> 5;
    const int warp_m = wid & 1;
    const int warp_n = wid >> 1;
    const int row0   = blockIdx.y * 128;
    const int col0   = blockIdx.x * 128;
    const int z      = blockIdx.z;

    const __half* __restrict__ Bh  = gpar.Bh[z];
    const float* __restrict__ bias = gpar.bias[z];
    const float cs = gpar.cscale[z];

    const uint32_t dyn0 = smem_u32(dsm);
    const uint32_t dyn  = (dyn0 + 1023) & ~1023u;

    const int nch = K / 64;

    auto load_chunk = [&](int c) {
        const uint32_t s = dyn + (c & 1) * STG;
        const int koff = c * 64;
        #pragma unroll
        for (int i = 0; i < 8; i++) {
            int lin = tid + i * 128;
            int r = lin >> 3, sg = lin & 7;
            uint32_t sw = sw128((uint32_t)(r * 128 + sg * 16));
            CPA16(s + sw, (const void*)(Ah + (long long)(row0 + r) * lda + koff + sg * 8));
        }
        #pragma unroll
        for (int i = 0; i < 8; i++) {
            int lin = tid + i * 128;
            int r = lin >> 3, sg = lin & 7;
            uint32_t sw = sw128((uint32_t)(r * 128 + sg * 16));
            CPA16(s + ABYTES + sw, (const void*)(Bh + (long long)(col0 + r) * ldb + koff + sg * 8));
        }
        CPA_COMMIT();
    };

    float acc[4][8][4];
    #pragma unroll
    for (int i = 0; i < 4; i++)
        #pragma unroll
        for (int j = 0; j < 8; j++)
            #pragma unroll
            for (int q = 0; q < 4; q++) acc[i][j][q] = 0.f;

    load_chunk(0);

    for (int c = 0; c < nch; c++) {
        if (c + 1 < nch) { load_chunk(c + 1); CPA_WAIT(1); }
        else             { CPA_WAIT(0); }
        __syncthreads();

        const uint32_t ah_ = dyn + (c & 1) * STG;
        const uint32_t bh_ = ah_ + ABYTES;

        #pragma unroll
        for (int ks = 0; ks < 4; ks++) {
            uint32_t bF[4][4];
            #pragma unroll
            for (int jn = 0; jn < 4; jn++) {
                const int q = lane >> 3, rr = lane & 7;
                int nr = warp_n * 64 + jn * 16 + ((q >> 1) << 3) + rr;
                uint32_t bo = (uint32_t)(nr * 128 + (ks * 16 + (q & 1) * 8) * 2);
                LDSM_X4(bF[jn], bh_ + sw128(bo));
            }
            uint32_t aF[4][4];
            #pragma unroll
            for (int im = 0; im < 4; im++) {
                int r = warp_m * 64 + im * 16 + (lane & 15);
                uint32_t bo = (uint32_t)(r * 128 + ks * 32 + (lane >> 4) * 16);
                LDSM_X4(aF[im], ah_ + sw128(bo));
            }
            #pragma unroll
            for (int im = 0; im < 4; im++) {
                #pragma unroll
                for (int jn = 0; jn < 4; jn++) {
                    MMA16816(acc[im][2 * jn],     aF[im], bF[jn][0], bF[jn][1]);
                    MMA16816(acc[im][2 * jn + 1], aF[im], bF[jn][2], bF[jn][3]);
                }
            }
        }
        __syncthreads();
    }

    const int g = lane >> 2, t = lane & 3;
    #pragma unroll
    for (int im = 0; im < 4; im++) {
        #pragma unroll
        for (int in = 0; in < 8; in++) {
            const float* ac = acc[im][in];
            const int n0 = col0 + warp_n * 64 + in * 8 + t * 2;
            #pragma unroll
            for (int half_ = 0; half_ < 2; half_++) {
                const int m = row0 + warp_m * 64 + im * 16 + g + half_ * 8;
                float v0 = ac[half_ * 2]     + bias[n0];
                float v1 = ac[half_ * 2 + 1] + bias[n0 + 1];
                if (EPI == 0) {
                    *(float2*)(gpar.Cf + (long long)m * ldc + n0) = make_float2(v0, v1);
                } else {
                    v0 *= cs; v1 *= cs;
                    int b = m >> 10, s = m & 1023, h = n0 >> 6, d = n0 & 63;
                    long long off = ((((long long)(b * NHEAD + h) << 10) + s) * HDIM) + d;
                    __half2 H; H.x = __float2half_rn(v0); H.y = __float2half_rn(v1);
                    *(__half2*)(gpar.Ch[z] + off) = H;
                }
            }
        }
    }
}

// ---------------------------------------------------------------------------
// Fused flash attention (R10/R12 config; Q pre-scaled by 1/8 upstream).
// ---------------------------------------------------------------------------
__global__ void __launch_bounds__(256, 2)
flash_attn(const __half* __restrict__ qh, const __half* __restrict__ kh,
           const __half* __restrict__ vh, __half* __restrict__ wah)
{
    extern __shared__ char dsm[];
    const int tid  = threadIdx.x;
    const int lane = tid & 31;
    const int wid  = tid >> 5;
    const int z    = blockIdx.x;
    const int qrow0 = blockIdx.y * 128;

    const uint32_t dyn0 = smem_u32(dsm);
    const uint32_t dyn  = (dyn0 + 1023) & ~1023u;
    const uint32_t sQh = dyn;
    const uint32_t kvb = dyn + 16384;

    const long long zoff = (long long)z * SEQ * HDIM;
    const __half* Qh = qh + zoff;
    const __half* Kh = kh + zoff;
    const __half* Vh = vh + zoff;

    #pragma unroll
    for (int i = 0; i < 4; i++) {
        int lin = tid + i * 256;
        int r = lin >> 3, sg = lin & 7;
        uint32_t sw = sw128((uint32_t)(r * 128 + sg * 16));
        CPA16(sQh + sw, (const void*)(Qh + (long long)(qrow0 + r) * HDIM + sg * 8));
    }
    CPA_COMMIT();

    auto load_kv = [&](int c) {
        uint32_t b = kvb + (c & 1) * 16384;
        int kv0 = c * 64;
        #pragma unroll
        for (int i = 0; i < 2; i++) {
            int lin = tid + i * 256;
            int r = lin >> 3, sg = lin & 7;
            uint32_t sw = sw128((uint32_t)(r * 128 + sg * 16));
            long long go = (long long)(kv0 + r) * HDIM + sg * 8;
            CPA16(b +        sw, (const void*)(Kh + go));
            CPA16(b + 8192 + sw, (const void*)(Vh + go));
        }
        CPA_COMMIT();
    };
    load_kv(0);

    const int g = lane >> 2, t = lane & 3;
    float O[8][4];
    #pragma unroll
    for (int j = 0; j < 8; j++)
        #pragma unroll
        for (int q = 0; q < 4; q++) O[j][q] = 0.f;
    float m0 = -1e30f, m1 = -1e30f, l0 = 0.f, l1 = 0.f;

    const int NKV = SEQ / 64;
    for (int c = 0; c < NKV; c++) {
        if (c + 1 < NKV) { load_kv(c + 1); CPA_WAIT(1); }
        else             { CPA_WAIT(0); }
        __syncthreads();

        const uint32_t base = kvb + (c & 1) * 16384;
        const uint32_t bKh = base, bVh = base + 8192;

        float S[8][4];
        #pragma unroll
        for (int j = 0; j < 8; j++)
            #pragma unroll
            for (int q = 0; q < 4; q++) S[j][q] = 0.f;

        // ---- S = (Q/8) K^T ----
        #pragma unroll
        for (int ks = 0; ks < 4; ks++) {
            uint32_t aH[4];
            {
                int r = wid * 16 + (lane & 15);
                uint32_t boff = (uint32_t)(r * 128 + ks * 32 + (lane >> 4) * 16);
                LDSM_X4(aH, sQh + sw128(boff));
            }
            #pragma unroll
            for (int gp = 0; gp < 2; gp++) {
                uint32_t bH0[4], bH1[4];
                const int q = lane >> 3, rr = lane & 7;
                int nr0 = (2 * gp)     * 16 + ((q >> 1) << 3) + rr;
                int nr1 = (2 * gp + 1) * 16 + ((q >> 1) << 3) + rr;
                uint32_t bo0 = (uint32_t)(nr0 * 128 + (ks * 16 + (q & 1) * 8) * 2);
                uint32_t bo1 = (uint32_t)(nr1 * 128 + (ks * 16 + (q & 1) * 8) * 2);
                LDSM_X4(bH0, bKh + sw128(bo0));
                LDSM_X4(bH1, bKh + sw128(bo1));
                MMA16816(S[4 * gp],     aH, bH0[0], bH0[1]);
                MMA16816(S[4 * gp + 1], aH, bH0[2], bH0[3]);
                MMA16816(S[4 * gp + 2], aH, bH1[0], bH1[1]);
                MMA16816(S[4 * gp + 3], aH, bH1[2], bH1[3]);
            }
        }

        // ---- online softmax ----
        float mx0 = -1e30f, mx1 = -1e30f;
        #pragma unroll
        for (int j = 0; j < 8; j++) {
            mx0 = fmaxf(mx0, fmaxf(S[j][0], S[j][1]));
            mx1 = fmaxf(mx1, fmaxf(S[j][2], S[j][3]));
        }
        mx0 = fmaxf(mx0, __shfl_xor_sync(0xffffffffu, mx0, 1));
        mx0 = fmaxf(mx0, __shfl_xor_sync(0xffffffffu, mx0, 2));
        mx1 = fmaxf(mx1, __shfl_xor_sync(0xffffffffu, mx1, 1));
        mx1 = fmaxf(mx1, __shfl_xor_sync(0xffffffffu, mx1, 2));
        float nm0 = fmaxf(m0, mx0), nm1 = fmaxf(m1, mx1);
        float c0 = __expf(m0 - nm0), c1 = __expf(m1 - nm1);
        m0 = nm0; m1 = nm1;

        uint32_t PH[4][4];
        float s0 = 0.f, s1 = 0.f;
        #pragma unroll
        for (int ck = 0; ck < 4; ck++) {
            float p00 = __expf(S[2 * ck][0] - nm0),   p01 = __expf(S[2 * ck][1] - nm0);
            float p02 = __expf(S[2 * ck][2] - nm1),   p03 = __expf(S[2 * ck][3] - nm1);
            float p10 = __expf(S[2 * ck + 1][0] - nm0), p11 = __expf(S[2 * ck + 1][1] - nm0);
            float p12 = __expf(S[2 * ck + 1][2] - nm1), p13 = __expf(S[2 * ck + 1][3] - nm1);
            s0 += p00 + p01 + p10 + p11;
            s1 += p02 + p03 + p12 + p13;
            pack_h2(p00, p01, PH[ck][0]);
            pack_h2(p02, p03, PH[ck][1]);
            pack_h2(p10, p11, PH[ck][2]);
            pack_h2(p12, p13, PH[ck][3]);
        }
        l0 = l0 * c0 + s0;
        l1 = l1 * c1 + s1;
        #pragma unroll
        for (int j = 0; j < 8; j++) {
            O[j][0] *= c0; O[j][1] *= c0; O[j][2] *= c1; O[j][3] *= c1;
        }

        // ---- O += P V ----
        #pragma unroll
        for (int ck = 0; ck < 4; ck++) {
            #pragma unroll
            for (int dp = 0; dp < 2; dp++) {
                uint32_t bH0[4], bH1[4];
                const int q = lane >> 3, rr = lane & 7;
                int kr = ck * 16 + (q & 1) * 8 + rr;
                int nc0 = (2 * dp)     * 16 + ((q >> 1) << 3);
                int nc1 = (2 * dp + 1) * 16 + ((q >> 1) << 3);
                uint32_t bo0 = (uint32_t)(kr * 128 + nc0 * 2);
                uint32_t bo1 = (uint32_t)(kr * 128 + nc1 * 2);
                LDSM_X4T(bH0, bVh + sw128(bo0));
                LDSM_X4T(bH1, bVh + sw128(bo1));
                MMA16816(O[4 * dp],     PH[ck], bH0[0], bH0[1]);
                MMA16816(O[4 * dp + 1], PH[ck], bH0[2], bH0[3]);
                MMA16816(O[4 * dp + 2], PH[ck], bH1[0], bH1[1]);
                MMA16816(O[4 * dp + 3], PH[ck], bH1[2], bH1[3]);
            }
        }
        __syncthreads();
    }

    l0 += __shfl_xor_sync(0xffffffffu, l0, 1);
    l0 += __shfl_xor_sync(0xffffffffu, l0, 2);
    l1 += __shfl_xor_sync(0xffffffffu, l1, 1);
    l1 += __shfl_xor_sync(0xffffffffu, l1, 2);
    float inv0 = 1.f / l0, inv1 = 1.f / l1;

    const int b = z >> 4, h = z & 15;
    const int r0 = qrow0 + wid * 16 + g;
    #pragma unroll
    for (int j = 0; j < 8; j++) {
        int d = j * 8 + t * 2;
        long long off0 = (((long long)(b << 10) + r0) << 10) + h * HDIM + d;
        long long off1 = (((long long)(b << 10) + r0 + 8) << 10) + h * HDIM + d;
        __half2 H0; H0.x = __float2half_rn(O[j][0] * inv0); H0.y = __float2half_rn(O[j][1] * inv0);
        __half2 H1; H1.x = __float2half_rn(O[j][2] * inv1); H1.y = __float2half_rn(O[j][3] * inv1);
        *(__half2*)(wah + off0) = H0;
        *(__half2*)(wah + off1) = H1;
    }
}

// ---------------------------------------------------------------------------
// merged fp32 -> fp16 conversion: 2 independent float4 per thread (ILP x2).
// Region boundaries (1M, 1.25M, 1.5M, 1.75M float4) are even, so a pair
// starting at an even index never straddles regions.
// ---------------------------------------------------------------------------
struct SplitP {
    const float* in[5];
    __half* hi[5];
};

__device__ __forceinline__ void cvt_store(const SplitP& p, int idx)
{
    int r, local;
    if (idx < (1 << 20)) { r = 0; local = idx; }
    else {
        int t2 = idx - (1 << 20);
        r = 1 + (t2 >> 18);
        local = t2 & ((1 << 18) - 1);
    }
    float4 v = ((const float4*)p.in[r])[local];
    __half2 H0; H0.x = __float2half_rn(v.x); H0.y = __float2half_rn(v.y);
    __half2 H1; H1.x = __float2half_rn(v.z); H1.y = __float2half_rn(v.w);
    ((__half2*)p.hi[r])[2 * local]     = H0;
    ((__half2*)p.hi[r])[2 * local + 1] = H1;
}

__global__ void __launch_bounds__(256)
split_all(SplitP p)
{
    int base = (blockIdx.x * 256 + threadIdx.x) * 2;
    cvt_store(p, base);
    cvt_store(p, base + 1);
}

// ---------------------------------------------------------------------------
extern "C" void kernel_launch(void* const* d_in, const int* in_sizes, int n_in,
                              void* d_out, int out_size)
{
    (void)in_sizes; (void)n_in; (void)out_size;
    const float* x  = (const float*)d_in[0];
    const float* Wq = (const float*)d_in[1];
    const float* bq = (const float*)d_in[2];
    const float* Wk = (const float*)d_in[3];
    const float* bk = (const float*)d_in[4];
    const float* Wv = (const float*)d_in[5];
    const float* bv = (const float*)d_in[6];
    const float* Wp = (const float*)d_in[7];
    const float* bp = (const float*)d_in[8];
    float* out = (float*)d_out;

    __half *xh, *wh, *qh, *kh, *vh, *wah;
    cudaGetSymbolAddress((void**)&xh,  g_xh);
    cudaGetSymbolAddress((void**)&wh,  g_wh);
    cudaGetSymbolAddress((void**)&qh,  g_qh);
    cudaGetSymbolAddress((void**)&kh,  g_kh);
    cudaGetSymbolAddress((void**)&vh,  g_vh);
    cudaGetSymbolAddress((void**)&wah, g_wah);

    const int SMGM = 2 * 32768 + 1024;             // 66560 (2 CTAs/SM)
    const int SMFA = 16384 + 2 * 16384 + 1024;     // 50176 (2 CTAs/SM)
    cudaFuncSetAttribute(tc_gemm<1>, cudaFuncAttributeMaxDynamicSharedMemorySize, SMGM);
    cudaFuncSetAttribute(tc_gemm<0>, cudaFuncAttributeMaxDynamicSharedMemorySize, SMGM);
    cudaFuncSetAttribute(flash_attn, cudaFuncAttributeMaxDynamicSharedMemorySize, SMFA);

    SplitP sp;
    sp.in[0] = x;  sp.hi[0] = xh;
    sp.in[1] = Wq; sp.hi[1] = wh + 0 * DIM * DIM;
    sp.in[2] = Wk; sp.hi[2] = wh + 1 * DIM * DIM;
    sp.in[3] = Wv; sp.hi[3] = wh + 2 * DIM * DIM;
    sp.in[4] = Wp; sp.hi[4] = wh + 3 * DIM * DIM;
    // total float4 count = 1M (x) + 4*256K (W) = 2M; 2 per thread -> 4096 blocks
    split_all<<<(2 * (1 << 20)) / (256 * 2), 256>>>(sp);

    // QKV projections (z selects weight set) -> fp16 [B,H,S,Hd]
    // Q output pre-scaled by 1/8 (softmax scale folded upstream)
    GParams gq = {};
    gq.Bh[0] = wh + 0 * DIM * DIM; gq.bias[0] = bq; gq.Ch[0] = qh; gq.cscale[0] = 0.125f;
    gq.Bh[1] = wh + 1 * DIM * DIM; gq.bias[1] = bk; gq.Ch[1] = kh; gq.cscale[1] = 1.0f;
    gq.Bh[2] = wh + 2 * DIM * DIM; gq.bias[2] = bv; gq.Ch[2] = vh; gq.cscale[2] = 1.0f;
    dim3 gp(DIM / 128, NTOK / 128, 3);
    tc_gemm<1><<<gp, 128, SMGM>>>(xh, gq, DIM, DIM, DIM, 0);

    dim3 gf(NBH, SEQ / 128);
    flash_attn<<<gf, 256, SMFA>>>(qh, kh, vh, wah);

    GParams go = {};
    go.Bh[0] = wh + 3 * DIM * DIM; go.bias[0] = bp; go.Cf = out; go.cscale[0] = 1.0f;
    dim3 gop(DIM / 128, NTOK / 128, 1);
    tc_gemm<0><<<gop, 128, SMGM>>>(wah, go, DIM, DIM, DIM, DIM);
}